// round 2
// baseline (speedup 1.0000x reference)
#include <cuda_runtime.h>
#include <math.h>

// Problem constants
constexpr int SEQ  = 2048;   // W
constexpr int CH   = 1024;   // BINS
constexpr int NB   = 16;     // BANDS
constexpr int DH   = 64;     // CH / NB
constexpr int CROP = 2048;

// ---------------- scratch (device globals; no allocation allowed) ----------------
__device__ float g_xq[SEQ * CH];
__device__ float g_xk[SEQ * CH];
__device__ float g_xv[SEQ * CH];
__device__ float g_q [SEQ * CH];
__device__ float g_k [SEQ * CH];
__device__ float g_v [SEQ * CH];
__device__ float g_o [SEQ * CH];
__device__ float g_a [(size_t)NB * SEQ * SEQ];   // softmax(A) scratch (268 MB)

// =================================================================================
// Generic fp32 GEMM: C[M,N] = A[M,K] * B[K,N], row-major. M%128==0, N%128==0, K%16==0
// 128x128 tile, 256 threads, 8x8 microtile.
// =================================================================================
__global__ __launch_bounds__(256) void gemm128(const float* __restrict__ A,
                                               const float* __restrict__ B,
                                               float* __restrict__ C,
                                               int M, int N, int K) {
    __shared__ float sA[16][132];   // [k][i], transposed
    __shared__ float sB[16][132];   // [k][j]
    const int tid = threadIdx.x;
    const int tx = tid & 15, ty = tid >> 4;
    const int i0 = blockIdx.y * 128, j0 = blockIdx.x * 128;

    float acc[8][8] = {};

    for (int k0 = 0; k0 < K; k0 += 16) {
        // A tile: 128 rows x 16 k  (512 float4)
        #pragma unroll
        for (int n = 0; n < 2; n++) {
            int f = tid + n * 256;
            int row = f >> 2, c4 = (f & 3) * 4;
            float4 a4 = *(const float4*)(A + (size_t)(i0 + row) * K + k0 + c4);
            sA[c4 + 0][row] = a4.x; sA[c4 + 1][row] = a4.y;
            sA[c4 + 2][row] = a4.z; sA[c4 + 3][row] = a4.w;
        }
        // B tile: 16 k x 128 cols (512 float4)
        #pragma unroll
        for (int n = 0; n < 2; n++) {
            int f = tid + n * 256;
            int row = f >> 5, j4 = (f & 31) * 4;
            *(float4*)&sB[row][j4] = *(const float4*)(B + (size_t)(k0 + row) * N + j0 + j4);
        }
        __syncthreads();
        #pragma unroll
        for (int k = 0; k < 16; k++) {
            float4 a0 = *(float4*)&sA[k][8 * ty];
            float4 a1 = *(float4*)&sA[k][8 * ty + 4];
            float4 b0 = *(float4*)&sB[k][8 * tx];
            float4 b1 = *(float4*)&sB[k][8 * tx + 4];
            float av[8] = {a0.x, a0.y, a0.z, a0.w, a1.x, a1.y, a1.z, a1.w};
            float bv[8] = {b0.x, b0.y, b0.z, b0.w, b1.x, b1.y, b1.z, b1.w};
            #pragma unroll
            for (int a = 0; a < 8; a++)
                #pragma unroll
                for (int b = 0; b < 8; b++)
                    acc[a][b] = fmaf(av[a], bv[b], acc[a][b]);
        }
        __syncthreads();
    }
    #pragma unroll
    for (int a = 0; a < 8; a++) {
        float* crow = C + (size_t)(i0 + 8 * ty + a) * N + j0 + 8 * tx;
        *(float4*)(crow)     = make_float4(acc[a][0], acc[a][1], acc[a][2], acc[a][3]);
        *(float4*)(crow + 4) = make_float4(acc[a][4], acc[a][5], acc[a][6], acc[a][7]);
    }
}

// =================================================================================
// Depthwise 3-tap conv along time (padding=1): y[t,c] = w0*x[t-1,c]+w1*x[t,c]+w2*x[t+1,c]
// =================================================================================
__global__ __launch_bounds__(256) void dwconv(const float* __restrict__ x,
                                              const float* __restrict__ wgt,
                                              float* __restrict__ y) {
    int idx = blockIdx.x * 256 + threadIdx.x;
    int c = idx & (CH - 1);
    int t = idx >> 10;
    float w0 = wgt[c * 3 + 0], w1 = wgt[c * 3 + 1], w2 = wgt[c * 3 + 2];
    float xm = (t > 0)       ? x[idx - CH] : 0.f;
    float x0 = x[idx];
    float xp = (t < SEQ - 1) ? x[idx + CH] : 0.f;
    y[idx] = fmaf(w0, xm, fmaf(w1, x0, w2 * xp));
}

// =================================================================================
// qk kernel: per band h,
//   qk[i,j] = ( q_i . k_j  +  relw[:,i] . q_j ) / 32 + prev[h,i,j]
// Implemented as a single K=128 inner product:
//   U[0:64][i]  = q[(i0+i), h*64+d]   (transposed)     U[64+d][i] = relw[d][i0+i]
//   V[0:64][j]  = k[(j0+j), h*64+d]   (transposed)     V[64+d][j] = q[(j0+j), h*64+d]
// 128x128 output tile, 256 threads, 8x8 microtile, 135 KB dyn smem.
// =================================================================================
__global__ __launch_bounds__(256) void qk_kernel(const float* __restrict__ q,
                                                 const float* __restrict__ k,
                                                 const float* __restrict__ relw,
                                                 const float* __restrict__ prev,
                                                 float* __restrict__ out) {
    extern __shared__ float sm[];
    float (*U)[132] = (float(*)[132])sm;                 // [128][132]
    float (*V)[132] = (float(*)[132])(sm + 128 * 132);   // [128][132]
    const int h  = blockIdx.z;
    const int i0 = blockIdx.y * 128, j0 = blockIdx.x * 128;
    const int tid = threadIdx.x;

    // ---- loads (global coalesced over the contiguous index) ----
    #pragma unroll 4
    for (int n = 0; n < 32; n++) {              // U: q_i^T (64 d x 128 i)
        int e = tid + n * 256;
        int i = e >> 6, d = e & 63;
        U[d][i] = q[(size_t)(i0 + i) * CH + h * DH + d];
    }
    #pragma unroll 4
    for (int n = 0; n < 32; n++) {              // U: relw slice (64 d x 128 i)
        int e = tid + n * 256;
        int d = e >> 7, i = e & 127;
        U[64 + d][i] = relw[(size_t)d * CROP + i0 + i];
    }
    #pragma unroll 4
    for (int n = 0; n < 32; n++) {              // V: k_j^T
        int e = tid + n * 256;
        int j = e >> 6, d = e & 63;
        V[d][j] = k[(size_t)(j0 + j) * CH + h * DH + d];
    }
    #pragma unroll 4
    for (int n = 0; n < 32; n++) {              // V: q_j^T
        int e = tid + n * 256;
        int j = e >> 6, d = e & 63;
        V[64 + d][j] = q[(size_t)(j0 + j) * CH + h * DH + d];
    }
    __syncthreads();

    const int tx = tid & 15, ty = tid >> 4;
    float acc[8][8] = {};
    #pragma unroll 4
    for (int dd = 0; dd < 128; dd++) {
        float4 u0 = *(float4*)&U[dd][8 * ty];
        float4 u1 = *(float4*)&U[dd][8 * ty + 4];
        float4 v0 = *(float4*)&V[dd][8 * tx];
        float4 v1 = *(float4*)&V[dd][8 * tx + 4];
        float uv[8] = {u0.x, u0.y, u0.z, u0.w, u1.x, u1.y, u1.z, u1.w};
        float vv[8] = {v0.x, v0.y, v0.z, v0.w, v1.x, v1.y, v1.z, v1.w};
        #pragma unroll
        for (int a = 0; a < 8; a++)
            #pragma unroll
            for (int b = 0; b < 8; b++)
                acc[a][b] = fmaf(uv[a], vv[b], acc[a][b]);
    }

    const float scale = 0.03125f;   // 1/sqrt(1024)
    #pragma unroll
    for (int a = 0; a < 8; a++) {
        size_t rowbase = ((size_t)h * SEQ + i0 + 8 * ty + a) * SEQ + j0 + 8 * tx;
        float4 p0 = *(const float4*)(prev + rowbase);
        float4 p1 = *(const float4*)(prev + rowbase + 4);
        *(float4*)(out + rowbase) = make_float4(
            fmaf(acc[a][0], scale, p0.x), fmaf(acc[a][1], scale, p0.y),
            fmaf(acc[a][2], scale, p0.z), fmaf(acc[a][3], scale, p0.w));
        *(float4*)(out + rowbase + 4) = make_float4(
            fmaf(acc[a][4], scale, p1.x), fmaf(acc[a][5], scale, p1.y),
            fmaf(acc[a][6], scale, p1.z), fmaf(acc[a][7], scale, p1.w));
    }
}

// =================================================================================
// Row softmax: one block per (row, band). 256 threads x 8 elements. In-place safe.
// =================================================================================
__global__ __launch_bounds__(256) void softmax_kernel(const float* __restrict__ qk,
                                                      float* __restrict__ a) {
    __shared__ float red[8];
    const size_t base = ((size_t)blockIdx.y * SEQ + blockIdx.x) * SEQ;
    const int tid = threadIdx.x;
    const int lane = tid & 31, wid = tid >> 5;

    const float4* p = (const float4*)(qk + base) + tid * 2;
    float4 r0 = p[0], r1 = p[1];

    float m = fmaxf(fmaxf(fmaxf(r0.x, r0.y), fmaxf(r0.z, r0.w)),
                    fmaxf(fmaxf(r1.x, r1.y), fmaxf(r1.z, r1.w)));
    #pragma unroll
    for (int o = 16; o > 0; o >>= 1) m = fmaxf(m, __shfl_xor_sync(~0u, m, o));
    if (lane == 0) red[wid] = m;
    __syncthreads();
    m = red[0];
    #pragma unroll
    for (int w = 1; w < 8; w++) m = fmaxf(m, red[w]);
    __syncthreads();

    r0.x = __expf(r0.x - m); r0.y = __expf(r0.y - m);
    r0.z = __expf(r0.z - m); r0.w = __expf(r0.w - m);
    r1.x = __expf(r1.x - m); r1.y = __expf(r1.y - m);
    r1.z = __expf(r1.z - m); r1.w = __expf(r1.w - m);

    float s = r0.x + r0.y + r0.z + r0.w + r1.x + r1.y + r1.z + r1.w;
    #pragma unroll
    for (int o = 16; o > 0; o >>= 1) s += __shfl_xor_sync(~0u, s, o);
    if (lane == 0) red[wid] = s;
    __syncthreads();
    s = red[0];
    #pragma unroll
    for (int w = 1; w < 8; w++) s += red[w];

    float inv = 1.0f / s;
    r0.x *= inv; r0.y *= inv; r0.z *= inv; r0.w *= inv;
    r1.x *= inv; r1.y *= inv; r1.z *= inv; r1.w *= inv;

    float4* q4 = (float4*)(a + base) + tid * 2;
    q4[0] = r0; q4[1] = r1;
}

// =================================================================================
// AV kernel: per band h, O[i, h*64+d] = sum_j A[h,i,j] * v[j, h*64+d]
// 128(i) x 64(d) tile, 256 threads (32 x 8), 4x8 microtile, K-loop over 2048.
// =================================================================================
__global__ __launch_bounds__(256) void av_kernel(const float* __restrict__ A,
                                                 const float* __restrict__ v,
                                                 float* __restrict__ o) {
    __shared__ float sA[16][132];   // [k][i]
    __shared__ float sB[16][68];    // [k][d]
    const int h  = blockIdx.y;
    const int i0 = blockIdx.x * 128;
    const float* Ah = A + (size_t)h * SEQ * SEQ;
    const int tid = threadIdx.x;
    const int tx = tid & 7, ty = tid >> 3;   // tx: d-micro(8), ty: i-micro base (32 rows of 4)

    float acc[4][8] = {};

    for (int k0 = 0; k0 < SEQ; k0 += 16) {
        #pragma unroll
        for (int n = 0; n < 2; n++) {           // A tile 128 x 16
            int f = tid + n * 256;
            int row = f >> 2, c4 = (f & 3) * 4;
            float4 a4 = *(const float4*)(Ah + (size_t)(i0 + row) * SEQ + k0 + c4);
            sA[c4 + 0][row] = a4.x; sA[c4 + 1][row] = a4.y;
            sA[c4 + 2][row] = a4.z; sA[c4 + 3][row] = a4.w;
        }
        {                                        // V tile 16 x 64
            int row = tid >> 4, j4 = (tid & 15) * 4;
            *(float4*)&sB[row][j4] = *(const float4*)(v + (size_t)(k0 + row) * CH + h * DH + j4);
        }
        __syncthreads();
        #pragma unroll
        for (int k = 0; k < 16; k++) {
            float4 a4 = *(float4*)&sA[k][4 * ty];
            float4 b0 = *(float4*)&sB[k][8 * tx];
            float4 b1 = *(float4*)&sB[k][8 * tx + 4];
            float avv[4] = {a4.x, a4.y, a4.z, a4.w};
            float bvv[8] = {b0.x, b0.y, b0.z, b0.w, b1.x, b1.y, b1.z, b1.w};
            #pragma unroll
            for (int a = 0; a < 4; a++)
                #pragma unroll
                for (int b = 0; b < 8; b++)
                    acc[a][b] = fmaf(avv[a], bvv[b], acc[a][b]);
        }
        __syncthreads();
    }
    #pragma unroll
    for (int a = 0; a < 4; a++) {
        float* orow = o + (size_t)(i0 + 4 * ty + a) * CH + h * DH + 8 * tx;
        *(float4*)(orow)     = make_float4(acc[a][0], acc[a][1], acc[a][2], acc[a][3]);
        *(float4*)(orow + 4) = make_float4(acc[a][4], acc[a][5], acc[a][6], acc[a][7]);
    }
}

// =================================================================================
extern "C" void kernel_launch(void* const* d_in, const int* in_sizes, int n_in,
                              void* d_out, int out_size) {
    const float* x    = (const float*)d_in[0];
    const float* prev = (const float*)d_in[1];
    const float* Wq   = (const float*)d_in[2];
    const float* Wk   = (const float*)d_in[3];
    const float* Wv   = (const float*)d_in[4];
    const float* Wo   = (const float*)d_in[5];
    const float* cq   = (const float*)d_in[6];
    const float* ck   = (const float*)d_in[7];
    const float* cv   = (const float*)d_in[8];
    const float* relw = (const float*)d_in[9];

    float* out0 = (float*)d_out;

    float *xq, *xk, *xv, *q, *k, *v, *o, *a;
    cudaGetSymbolAddress((void**)&xq, g_xq);
    cudaGetSymbolAddress((void**)&xk, g_xk);
    cudaGetSymbolAddress((void**)&xv, g_xv);
    cudaGetSymbolAddress((void**)&q,  g_q);
    cudaGetSymbolAddress((void**)&k,  g_k);
    cudaGetSymbolAddress((void**)&v,  g_v);
    cudaGetSymbolAddress((void**)&o,  g_o);
    cudaGetSymbolAddress((void**)&a,  g_a);

    // Tuple output layout assumption: [o@Wo (2048*1024), qk (16*2048*2048)].
    // Defensive: if out is too small for both, keep qk in scratch.
    const long long need = (long long)SEQ * CH + (long long)NB * SEQ * SEQ;
    float* qk_dst = ((long long)out_size >= need) ? (out0 + (size_t)SEQ * CH) : a;

    const int SMEM_QK = 2 * 128 * 132 * (int)sizeof(float);   // 135168
    cudaFuncSetAttribute(qk_kernel, cudaFuncAttributeMaxDynamicSharedMemorySize, SMEM_QK);

    dim3 gW(CH / 128, SEQ / 128);          // 8 x 16
    gemm128<<<gW, 256>>>(x, Wq, xq, SEQ, CH, CH);
    gemm128<<<gW, 256>>>(x, Wk, xk, SEQ, CH, CH);
    gemm128<<<gW, 256>>>(x, Wv, xv, SEQ, CH, CH);

    dwconv<<<SEQ * CH / 256, 256>>>(xq, cq, q);
    dwconv<<<SEQ * CH / 256, 256>>>(xk, ck, k);
    dwconv<<<SEQ * CH / 256, 256>>>(xv, cv, v);

    dim3 gQK(SEQ / 128, SEQ / 128, NB);    // 16 x 16 x 16
    qk_kernel<<<gQK, 256, SMEM_QK>>>(q, k, relw, prev, qk_dst);

    dim3 gSM(SEQ, NB);                     // 2048 x 16 (in-place safe if qk_dst==a)
    softmax_kernel<<<gSM, 256>>>(qk_dst, a);

    dim3 gAV(SEQ / 128, NB);               // 16 x 16
    av_kernel<<<gAV, 256>>>(a, v, o);

    gemm128<<<gW, 256>>>(o, Wo, out0, SEQ, CH, CH);
}

// round 4
// speedup vs baseline: 2.3189x; 2.3189x over previous
#include <cuda_runtime.h>
#include <math.h>

constexpr int SEQ  = 2048;
constexpr int CH   = 1024;
constexpr int NB   = 16;
constexpr int DH   = 64;
constexpr int CROP = 2048;

// ---------------- scratch ----------------
__device__ float g_xq[SEQ * CH];
__device__ float g_xk[SEQ * CH];
__device__ float g_xv[SEQ * CH];
__device__ float g_q [SEQ * CH];
__device__ float g_k [SEQ * CH];
__device__ float g_v [SEQ * CH];
__device__ float g_o [SEQ * CH];
__device__ float g_a [(size_t)NB * SEQ * SEQ];

// ---------------- tf32 helpers ----------------
__device__ __forceinline__ unsigned f2t(float f) {
    unsigned u; asm("cvt.rna.tf32.f32 %0, %1;" : "=r"(u) : "f"(f)); return u;
}
__device__ __forceinline__ void mma8(float c[4], const unsigned a[4], const unsigned b[2]) {
    asm volatile(
        "mma.sync.aligned.m16n8k8.row.col.f32.tf32.tf32.f32 "
        "{%0,%1,%2,%3},{%4,%5,%6,%7},{%8,%9},{%0,%1,%2,%3};"
        : "+f"(c[0]), "+f"(c[1]), "+f"(c[2]), "+f"(c[3])
        : "r"(a[0]), "r"(a[1]), "r"(a[2]), "r"(a[3]), "r"(b[0]), "r"(b[1]));
}

// =================================================================================
// Batched TF32 GEMM: C[z] = A @ B[z], A:[2048x1024], B:[1024x1024] row-major.
// 128x128 tile, BK=32, 256 threads (8 warps as 2x4), register-prefetch pipeline.
// =================================================================================
__global__ __launch_bounds__(256) void gemm_xw(
    const float* __restrict__ A,
    const float* __restrict__ B0, const float* __restrict__ B1, const float* __restrict__ B2,
    float* __restrict__ C0, float* __restrict__ C1, float* __restrict__ C2) {
    __shared__ unsigned sA[128][36];   // [m][k], stride 36 (4 mod 32)
    __shared__ unsigned sB[32][136];   // [k][n], stride 136 (8 mod 32)

    const float* B = blockIdx.z == 0 ? B0 : (blockIdx.z == 1 ? B1 : B2);
    float*       C = blockIdx.z == 0 ? C0 : (blockIdx.z == 1 ? C1 : C2);

    const int tid = threadIdx.x, lane = tid & 31, wid = tid >> 5;
    const int i0 = blockIdx.y * 128, j0 = blockIdx.x * 128;
    const int wm0 = (wid >> 2) * 64, wn0 = (wid & 3) * 32;
    const int g = lane >> 2, l = lane & 3;

    float4 pa[4], pb[4];

    auto loadT = [&](int k0) {
        #pragma unroll
        for (int n = 0; n < 4; n++) {
            int f = tid + n * 256, r = f >> 3, c = (f & 7) * 4;
            pa[n] = *(const float4*)(A + (size_t)(i0 + r) * CH + k0 + c);
        }
        #pragma unroll
        for (int n = 0; n < 4; n++) {
            int f = tid + n * 256, r = f >> 5, c = (f & 31) * 4;
            pb[n] = *(const float4*)(B + (size_t)(k0 + r) * CH + j0 + c);
        }
    };
    auto storeT = [&]() {
        #pragma unroll
        for (int n = 0; n < 4; n++) {
            int f = tid + n * 256, r = f >> 3, c = (f & 7) * 4;
            sA[r][c] = f2t(pa[n].x); sA[r][c + 1] = f2t(pa[n].y);
            sA[r][c + 2] = f2t(pa[n].z); sA[r][c + 3] = f2t(pa[n].w);
        }
        #pragma unroll
        for (int n = 0; n < 4; n++) {
            int f = tid + n * 256, r = f >> 5, c = (f & 31) * 4;
            sB[r][c] = f2t(pb[n].x); sB[r][c + 1] = f2t(pb[n].y);
            sB[r][c + 2] = f2t(pb[n].z); sB[r][c + 3] = f2t(pb[n].w);
        }
    };

    float acc[4][4][4] = {};
    loadT(0); storeT(); __syncthreads();

    for (int k0 = 0; k0 < CH; k0 += 32) {
        bool nx = (k0 + 32) < CH;
        if (nx) loadT(k0 + 32);
        #pragma unroll
        for (int ks = 0; ks < 4; ks++) {
            int kk = ks * 8;
            unsigned af[4][4], bf[4][2];
            #pragma unroll
            for (int mt = 0; mt < 4; mt++) {
                int m = wm0 + mt * 16 + g;
                af[mt][0] = sA[m][kk + l];       af[mt][1] = sA[m + 8][kk + l];
                af[mt][2] = sA[m][kk + 4 + l];   af[mt][3] = sA[m + 8][kk + 4 + l];
            }
            #pragma unroll
            for (int nt = 0; nt < 4; nt++) {
                int n = wn0 + nt * 8 + g;
                bf[nt][0] = sB[kk + l][n];       bf[nt][1] = sB[kk + 4 + l][n];
            }
            #pragma unroll
            for (int mt = 0; mt < 4; mt++)
                #pragma unroll
                for (int nt = 0; nt < 4; nt++) mma8(acc[mt][nt], af[mt], bf[nt]);
        }
        __syncthreads();
        if (nx) { storeT(); __syncthreads(); }
    }

    #pragma unroll
    for (int mt = 0; mt < 4; mt++)
        #pragma unroll
        for (int nt = 0; nt < 4; nt++) {
            int m = i0 + wm0 + mt * 16 + g, n = j0 + wn0 + nt * 8 + 2 * l;
            *(float2*)(C + (size_t)m * CH + n) =
                make_float2(acc[mt][nt][0], acc[mt][nt][1]);
            *(float2*)(C + (size_t)(m + 8) * CH + n) =
                make_float2(acc[mt][nt][2], acc[mt][nt][3]);
        }
}

// =================================================================================
// Batched depthwise 3-tap conv: z in {0,1,2} selects (x, w, y) triple.
// =================================================================================
__global__ __launch_bounds__(256) void dwconv3(
    const float* __restrict__ x0, const float* __restrict__ x1, const float* __restrict__ x2,
    const float* __restrict__ w0p, const float* __restrict__ w1p, const float* __restrict__ w2p,
    float* __restrict__ y0, float* __restrict__ y1, float* __restrict__ y2) {
    int z = blockIdx.y;
    const float* x = z == 0 ? x0 : (z == 1 ? x1 : x2);
    const float* wgt = z == 0 ? w0p : (z == 1 ? w1p : w2p);
    float* y = z == 0 ? y0 : (z == 1 ? y1 : y2);

    int idx = blockIdx.x * 256 + threadIdx.x;
    int c = idx & (CH - 1);
    int t = idx >> 10;
    float w0 = wgt[c * 3 + 0], w1 = wgt[c * 3 + 1], w2 = wgt[c * 3 + 2];
    float xm = (t > 0)       ? x[idx - CH] : 0.f;
    float xc = x[idx];
    float xp = (t < SEQ - 1) ? x[idx + CH] : 0.f;
    y[idx] = fmaf(w0, xm, fmaf(w1, xc, w2 * xp));
}

// =================================================================================
// qk kernel (TF32): per band h,
//   qk[i,j] = ( q_i.k_j + relw[:,i].q_j ) / 32 + prev[h,i,j]   (fused K=128 GEMM)
// U[i][0:64]=q_i, U[i][64+d]=relw[d][i]; V[0:64][j]=k_j^T, V[64+d][j]=q[j,d].
// 128x128 tile, 8 warps (2x4), operands fully resident in smem.
// =================================================================================
__global__ __launch_bounds__(256) void qk_tf32(
    const float* __restrict__ q, const float* __restrict__ k,
    const float* __restrict__ relw, const float* __restrict__ prev,
    float* __restrict__ out) {
    extern __shared__ unsigned smqk[];
    unsigned (*sU)[132] = (unsigned(*)[132])smqk;                  // [i][kk] stride 132
    unsigned (*sV)[136] = (unsigned(*)[136])(smqk + 128 * 132);    // [kk][j] stride 136

    const int h = blockIdx.z, i0 = blockIdx.y * 128, j0 = blockIdx.x * 128;
    const int tid = threadIdx.x, lane = tid & 31, wid = tid >> 5;
    const int g = lane >> 2, l = lane & 3;

    // U q-part: [i][d]
    #pragma unroll
    for (int n = 0; n < 8; n++) {
        int f = tid + n * 256, i = f >> 4, d = (f & 15) * 4;
        float4 v4 = *(const float4*)(q + (size_t)(i0 + i) * CH + h * DH + d);
        sU[i][d] = f2t(v4.x); sU[i][d + 1] = f2t(v4.y);
        sU[i][d + 2] = f2t(v4.z); sU[i][d + 3] = f2t(v4.w);
    }
    // U relw-part: [i][64+d] from relw[d][i0+i]
    #pragma unroll
    for (int n = 0; n < 8; n++) {
        int f = tid + n * 256, d = f >> 5, i = (f & 31) * 4;
        float4 v4 = *(const float4*)(relw + (size_t)d * CROP + i0 + i);
        sU[i][64 + d] = f2t(v4.x); sU[i + 1][64 + d] = f2t(v4.y);
        sU[i + 2][64 + d] = f2t(v4.z); sU[i + 3][64 + d] = f2t(v4.w);
    }
    // V k-part: [d][j]
    #pragma unroll
    for (int n = 0; n < 8; n++) {
        int f = tid + n * 256, j = f >> 4, d = (f & 15) * 4;
        float4 v4 = *(const float4*)(k + (size_t)(j0 + j) * CH + h * DH + d);
        sV[d][j] = f2t(v4.x); sV[d + 1][j] = f2t(v4.y);
        sV[d + 2][j] = f2t(v4.z); sV[d + 3][j] = f2t(v4.w);
    }
    // V q-part: [64+d][j]
    #pragma unroll
    for (int n = 0; n < 8; n++) {
        int f = tid + n * 256, j = f >> 4, d = (f & 15) * 4;
        float4 v4 = *(const float4*)(q + (size_t)(j0 + j) * CH + h * DH + d);
        sV[64 + d][j] = f2t(v4.x); sV[64 + d + 1][j] = f2t(v4.y);
        sV[64 + d + 2][j] = f2t(v4.z); sV[64 + d + 3][j] = f2t(v4.w);
    }
    __syncthreads();

    const int wm0 = (wid >> 2) * 64, wn0 = (wid & 3) * 32;
    float acc[4][4][4] = {};
    #pragma unroll 4
    for (int ks = 0; ks < 16; ks++) {
        int kk = ks * 8;
        unsigned af[4][4], bf[4][2];
        #pragma unroll
        for (int mt = 0; mt < 4; mt++) {
            int m = wm0 + mt * 16 + g;
            af[mt][0] = sU[m][kk + l];       af[mt][1] = sU[m + 8][kk + l];
            af[mt][2] = sU[m][kk + 4 + l];   af[mt][3] = sU[m + 8][kk + 4 + l];
        }
        #pragma unroll
        for (int nt = 0; nt < 4; nt++) {
            int n = wn0 + nt * 8 + g;
            bf[nt][0] = sV[kk + l][n];       bf[nt][1] = sV[kk + 4 + l][n];
        }
        #pragma unroll
        for (int mt = 0; mt < 4; mt++)
            #pragma unroll
            for (int nt = 0; nt < 4; nt++) mma8(acc[mt][nt], af[mt], bf[nt]);
    }

    const float scale = 0.03125f;   // 1/sqrt(1024)
    #pragma unroll
    for (int mt = 0; mt < 4; mt++)
        #pragma unroll
        for (int nt = 0; nt < 4; nt++) {
            int m = i0 + wm0 + mt * 16 + g, n = j0 + wn0 + nt * 8 + 2 * l;
            size_t o0 = ((size_t)h * SEQ + m) * SEQ + n;
            size_t o1 = o0 + (size_t)8 * SEQ;
            float2 p0 = *(const float2*)(prev + o0);
            float2 p1 = *(const float2*)(prev + o1);
            *(float2*)(out + o0) = make_float2(fmaf(acc[mt][nt][0], scale, p0.x),
                                               fmaf(acc[mt][nt][1], scale, p0.y));
            *(float2*)(out + o1) = make_float2(fmaf(acc[mt][nt][2], scale, p1.x),
                                               fmaf(acc[mt][nt][3], scale, p1.y));
        }
}

// =================================================================================
// Row softmax.
// =================================================================================
__global__ __launch_bounds__(256) void softmax_kernel(const float* __restrict__ qk,
                                                      float* __restrict__ a) {
    __shared__ float red[8];
    const size_t base = ((size_t)blockIdx.y * SEQ + blockIdx.x) * SEQ;
    const int tid = threadIdx.x;
    const int lane = tid & 31, wid = tid >> 5;

    const float4* p = (const float4*)(qk + base) + tid * 2;
    float4 r0 = p[0], r1 = p[1];

    float m = fmaxf(fmaxf(fmaxf(r0.x, r0.y), fmaxf(r0.z, r0.w)),
                    fmaxf(fmaxf(r1.x, r1.y), fmaxf(r1.z, r1.w)));
    #pragma unroll
    for (int o = 16; o > 0; o >>= 1) m = fmaxf(m, __shfl_xor_sync(~0u, m, o));
    if (lane == 0) red[wid] = m;
    __syncthreads();
    m = red[0];
    #pragma unroll
    for (int w = 1; w < 8; w++) m = fmaxf(m, red[w]);
    __syncthreads();

    r0.x = __expf(r0.x - m); r0.y = __expf(r0.y - m);
    r0.z = __expf(r0.z - m); r0.w = __expf(r0.w - m);
    r1.x = __expf(r1.x - m); r1.y = __expf(r1.y - m);
    r1.z = __expf(r1.z - m); r1.w = __expf(r1.w - m);

    float s = r0.x + r0.y + r0.z + r0.w + r1.x + r1.y + r1.z + r1.w;
    #pragma unroll
    for (int o = 16; o > 0; o >>= 1) s += __shfl_xor_sync(~0u, s, o);
    if (lane == 0) red[wid] = s;
    __syncthreads();
    s = red[0];
    #pragma unroll
    for (int w = 1; w < 8; w++) s += red[w];

    float inv = 1.0f / s;
    r0.x *= inv; r0.y *= inv; r0.z *= inv; r0.w *= inv;
    r1.x *= inv; r1.y *= inv; r1.z *= inv; r1.w *= inv;

    float4* q4 = (float4*)(a + base) + tid * 2;
    q4[0] = r0; q4[1] = r1;
}

// =================================================================================
// AV kernel (TF32): per band h, O[i, h*64+d] = sum_j A[h,i,j] * v[j, h*64+d].
// 128x64 tile, BK=32, 8 warps (4x2), register-prefetch pipeline.
// FIXED: A tile is 128x32 = 1024 float4 -> 4 float4 per thread (was 1).
// =================================================================================
__global__ __launch_bounds__(256) void av_tf32(const float* __restrict__ A,
                                               const float* __restrict__ v,
                                               float* __restrict__ o) {
    __shared__ unsigned sA[128][36];   // [i][k]
    __shared__ unsigned sB[32][72];    // [k][d], stride 72 (8 mod 32)
    const int h = blockIdx.y, i0 = blockIdx.x * 128;
    const float* Ah = A + (size_t)h * SEQ * SEQ;
    const int tid = threadIdx.x, lane = tid & 31, wid = tid >> 5;
    const int g = lane >> 2, l = lane & 3;
    const int wm0 = (wid >> 1) * 32, wn0 = (wid & 1) * 32;

    float4 pa[4], pb[2];
    auto loadT = [&](int k0) {
        #pragma unroll
        for (int n = 0; n < 4; n++) {
            int f = tid + n * 256, r = f >> 3, c = (f & 7) * 4;
            pa[n] = *(const float4*)(Ah + (size_t)(i0 + r) * SEQ + k0 + c);
        }
        #pragma unroll
        for (int n = 0; n < 2; n++) {
            int f = tid + n * 256, rr = f >> 4, cc = (f & 15) * 4;
            pb[n] = *(const float4*)(v + (size_t)(k0 + rr) * CH + h * DH + cc);
        }
    };
    auto storeT = [&]() {
        #pragma unroll
        for (int n = 0; n < 4; n++) {
            int f = tid + n * 256, r = f >> 3, c = (f & 7) * 4;
            sA[r][c] = f2t(pa[n].x); sA[r][c + 1] = f2t(pa[n].y);
            sA[r][c + 2] = f2t(pa[n].z); sA[r][c + 3] = f2t(pa[n].w);
        }
        #pragma unroll
        for (int n = 0; n < 2; n++) {
            int f = tid + n * 256, rr = f >> 4, cc = (f & 15) * 4;
            sB[rr][cc] = f2t(pb[n].x); sB[rr][cc + 1] = f2t(pb[n].y);
            sB[rr][cc + 2] = f2t(pb[n].z); sB[rr][cc + 3] = f2t(pb[n].w);
        }
    };

    float acc[2][4][4] = {};
    loadT(0); storeT(); __syncthreads();

    for (int k0 = 0; k0 < SEQ; k0 += 32) {
        bool nx = (k0 + 32) < SEQ;
        if (nx) loadT(k0 + 32);
        #pragma unroll
        for (int ks = 0; ks < 4; ks++) {
            int kk = ks * 8;
            unsigned af[2][4], bf[4][2];
            #pragma unroll
            for (int mt = 0; mt < 2; mt++) {
                int m = wm0 + mt * 16 + g;
                af[mt][0] = sA[m][kk + l];       af[mt][1] = sA[m + 8][kk + l];
                af[mt][2] = sA[m][kk + 4 + l];   af[mt][3] = sA[m + 8][kk + 4 + l];
            }
            #pragma unroll
            for (int nt = 0; nt < 4; nt++) {
                int n = wn0 + nt * 8 + g;
                bf[nt][0] = sB[kk + l][n];       bf[nt][1] = sB[kk + 4 + l][n];
            }
            #pragma unroll
            for (int mt = 0; mt < 2; mt++)
                #pragma unroll
                for (int nt = 0; nt < 4; nt++) mma8(acc[mt][nt], af[mt], bf[nt]);
        }
        __syncthreads();
        if (nx) { storeT(); __syncthreads(); }
    }

    #pragma unroll
    for (int mt = 0; mt < 2; mt++)
        #pragma unroll
        for (int nt = 0; nt < 4; nt++) {
            int m = i0 + wm0 + mt * 16 + g, n = wn0 + nt * 8 + 2 * l;
            *(float2*)(o + (size_t)m * CH + h * DH + n) =
                make_float2(acc[mt][nt][0], acc[mt][nt][1]);
            *(float2*)(o + (size_t)(m + 8) * CH + h * DH + n) =
                make_float2(acc[mt][nt][2], acc[mt][nt][3]);
        }
}

// =================================================================================
extern "C" void kernel_launch(void* const* d_in, const int* in_sizes, int n_in,
                              void* d_out, int out_size) {
    const float* x    = (const float*)d_in[0];
    const float* prev = (const float*)d_in[1];
    const float* Wq   = (const float*)d_in[2];
    const float* Wk   = (const float*)d_in[3];
    const float* Wv   = (const float*)d_in[4];
    const float* Wo   = (const float*)d_in[5];
    const float* cq   = (const float*)d_in[6];
    const float* ck   = (const float*)d_in[7];
    const float* cv   = (const float*)d_in[8];
    const float* relw = (const float*)d_in[9];

    float* out0 = (float*)d_out;

    float *xq, *xk, *xv, *q, *k, *v, *o, *a;
    cudaGetSymbolAddress((void**)&xq, g_xq);
    cudaGetSymbolAddress((void**)&xk, g_xk);
    cudaGetSymbolAddress((void**)&xv, g_xv);
    cudaGetSymbolAddress((void**)&q,  g_q);
    cudaGetSymbolAddress((void**)&k,  g_k);
    cudaGetSymbolAddress((void**)&v,  g_v);
    cudaGetSymbolAddress((void**)&o,  g_o);
    cudaGetSymbolAddress((void**)&a,  g_a);

    const long long need = (long long)SEQ * CH + (long long)NB * SEQ * SEQ;
    float* qk_dst = ((long long)out_size >= need) ? (out0 + (size_t)SEQ * CH) : a;

    const int SMEM_QK = (128 * 132 + 128 * 136) * (int)sizeof(unsigned);  // 137216
    cudaFuncSetAttribute(qk_tf32, cudaFuncAttributeMaxDynamicSharedMemorySize, SMEM_QK);

    // x @ {Wq, Wk, Wv}  (batched over z)
    gemm_xw<<<dim3(CH / 128, SEQ / 128, 3), 256>>>(x, Wq, Wk, Wv, xq, xk, xv);

    // depthwise conv x3 (batched over z)
    dwconv3<<<dim3(SEQ * CH / 256, 3), 256>>>(xq, xk, xv, cq, ck, cv, q, k, v);

    // fused qk
    qk_tf32<<<dim3(SEQ / 128, SEQ / 128, NB), 256, SMEM_QK>>>(q, k, relw, prev, qk_dst);

    // softmax
    softmax_kernel<<<dim3(SEQ, NB), 256>>>(qk_dst, a);

    // A @ V
    av_tf32<<<dim3(SEQ / 128, NB), 256>>>(a, v, o);

    // final @ Wo
    gemm_xw<<<dim3(CH / 128, SEQ / 128, 1), 256>>>(o, Wo, Wo, Wo, out0, out0, out0);
}

// round 5
// speedup vs baseline: 2.3593x; 1.0174x over previous
#include <cuda_runtime.h>
#include <math.h>

constexpr int SEQ  = 2048;
constexpr int CH   = 1024;
constexpr int NB   = 16;
constexpr int DH   = 64;
constexpr int CROP = 2048;

// ---------------- scratch ----------------
__device__ float g_xq[SEQ * CH];
__device__ float g_xk[SEQ * CH];
__device__ float g_xv[SEQ * CH];
__device__ float g_q [SEQ * CH];
__device__ float g_k [SEQ * CH];
__device__ float g_v [SEQ * CH];
__device__ float g_o [SEQ * CH];
__device__ float g_qk[(size_t)NB * SEQ * SEQ];   // fallback if out buffer too small

// ---------------- tf32 helpers ----------------
__device__ __forceinline__ unsigned f2t(float f) {
    unsigned u; asm("cvt.rna.tf32.f32 %0, %1;" : "=r"(u) : "f"(f)); return u;
}
__device__ __forceinline__ void mma8(float c[4], const unsigned a[4], const unsigned b[2]) {
    asm volatile(
        "mma.sync.aligned.m16n8k8.row.col.f32.tf32.tf32.f32 "
        "{%0,%1,%2,%3},{%4,%5,%6,%7},{%8,%9},{%0,%1,%2,%3};"
        : "+f"(c[0]), "+f"(c[1]), "+f"(c[2]), "+f"(c[3])
        : "r"(a[0]), "r"(a[1]), "r"(a[2]), "r"(a[3]), "r"(b[0]), "r"(b[1]));
}

// =================================================================================
// Batched TF32 GEMM: C[z] = A @ B[z], A:[2048x1024], B:[1024x1024] row-major.
// =================================================================================
__global__ __launch_bounds__(256) void gemm_xw(
    const float* __restrict__ A,
    const float* __restrict__ B0, const float* __restrict__ B1, const float* __restrict__ B2,
    float* __restrict__ C0, float* __restrict__ C1, float* __restrict__ C2) {
    __shared__ unsigned sA[128][36];
    __shared__ unsigned sB[32][136];

    const float* B = blockIdx.z == 0 ? B0 : (blockIdx.z == 1 ? B1 : B2);
    float*       C = blockIdx.z == 0 ? C0 : (blockIdx.z == 1 ? C1 : C2);

    const int tid = threadIdx.x, lane = tid & 31, wid = tid >> 5;
    const int i0 = blockIdx.y * 128, j0 = blockIdx.x * 128;
    const int wm0 = (wid >> 2) * 64, wn0 = (wid & 3) * 32;
    const int g = lane >> 2, l = lane & 3;

    float4 pa[4], pb[4];

    auto loadT = [&](int k0) {
        #pragma unroll
        for (int n = 0; n < 4; n++) {
            int f = tid + n * 256, r = f >> 3, c = (f & 7) * 4;
            pa[n] = *(const float4*)(A + (size_t)(i0 + r) * CH + k0 + c);
        }
        #pragma unroll
        for (int n = 0; n < 4; n++) {
            int f = tid + n * 256, r = f >> 5, c = (f & 31) * 4;
            pb[n] = *(const float4*)(B + (size_t)(k0 + r) * CH + j0 + c);
        }
    };
    auto storeT = [&]() {
        #pragma unroll
        for (int n = 0; n < 4; n++) {
            int f = tid + n * 256, r = f >> 3, c = (f & 7) * 4;
            sA[r][c] = f2t(pa[n].x); sA[r][c + 1] = f2t(pa[n].y);
            sA[r][c + 2] = f2t(pa[n].z); sA[r][c + 3] = f2t(pa[n].w);
        }
        #pragma unroll
        for (int n = 0; n < 4; n++) {
            int f = tid + n * 256, r = f >> 5, c = (f & 31) * 4;
            sB[r][c] = f2t(pb[n].x); sB[r][c + 1] = f2t(pb[n].y);
            sB[r][c + 2] = f2t(pb[n].z); sB[r][c + 3] = f2t(pb[n].w);
        }
    };

    float acc[4][4][4] = {};
    loadT(0); storeT(); __syncthreads();

    for (int k0 = 0; k0 < CH; k0 += 32) {
        bool nx = (k0 + 32) < CH;
        if (nx) loadT(k0 + 32);
        #pragma unroll
        for (int ks = 0; ks < 4; ks++) {
            int kk = ks * 8;
            unsigned af[4][4], bf[4][2];
            #pragma unroll
            for (int mt = 0; mt < 4; mt++) {
                int m = wm0 + mt * 16 + g;
                af[mt][0] = sA[m][kk + l];       af[mt][1] = sA[m + 8][kk + l];
                af[mt][2] = sA[m][kk + 4 + l];   af[mt][3] = sA[m + 8][kk + 4 + l];
            }
            #pragma unroll
            for (int nt = 0; nt < 4; nt++) {
                int n = wn0 + nt * 8 + g;
                bf[nt][0] = sB[kk + l][n];       bf[nt][1] = sB[kk + 4 + l][n];
            }
            #pragma unroll
            for (int mt = 0; mt < 4; mt++)
                #pragma unroll
                for (int nt = 0; nt < 4; nt++) mma8(acc[mt][nt], af[mt], bf[nt]);
        }
        __syncthreads();
        if (nx) { storeT(); __syncthreads(); }
    }

    #pragma unroll
    for (int mt = 0; mt < 4; mt++)
        #pragma unroll
        for (int nt = 0; nt < 4; nt++) {
            int m = i0 + wm0 + mt * 16 + g, n = j0 + wn0 + nt * 8 + 2 * l;
            *(float2*)(C + (size_t)m * CH + n) =
                make_float2(acc[mt][nt][0], acc[mt][nt][1]);
            *(float2*)(C + (size_t)(m + 8) * CH + n) =
                make_float2(acc[mt][nt][2], acc[mt][nt][3]);
        }
}

// =================================================================================
// Batched depthwise 3-tap conv.
// =================================================================================
__global__ __launch_bounds__(256) void dwconv3(
    const float* __restrict__ x0, const float* __restrict__ x1, const float* __restrict__ x2,
    const float* __restrict__ w0p, const float* __restrict__ w1p, const float* __restrict__ w2p,
    float* __restrict__ y0, float* __restrict__ y1, float* __restrict__ y2) {
    int z = blockIdx.y;
    const float* x = z == 0 ? x0 : (z == 1 ? x1 : x2);
    const float* wgt = z == 0 ? w0p : (z == 1 ? w1p : w2p);
    float* y = z == 0 ? y0 : (z == 1 ? y1 : y2);

    int idx = blockIdx.x * 256 + threadIdx.x;
    int c = idx & (CH - 1);
    int t = idx >> 10;
    float w0 = wgt[c * 3 + 0], w1 = wgt[c * 3 + 1], w2 = wgt[c * 3 + 2];
    float xm = (t > 0)       ? x[idx - CH] : 0.f;
    float xc = x[idx];
    float xp = (t < SEQ - 1) ? x[idx + CH] : 0.f;
    y[idx] = fmaf(w0, xm, fmaf(w1, xc, w2 * xp));
}

// =================================================================================
// qk kernel (TF32), BK=64 x 2 chunks (smem 68KB -> 2 blocks/SM):
//   chunk0: U=q_i[d], V=k_j^T          chunk1: U=relw[d][i], V=q_j^T
//   qk[i,j] = (sum) / 32 + prev[h,i,j]
// =================================================================================
__global__ __launch_bounds__(256) void qk_tf32(
    const float* __restrict__ q, const float* __restrict__ k,
    const float* __restrict__ relw, const float* __restrict__ prev,
    float* __restrict__ out) {
    extern __shared__ unsigned smqk[];
    unsigned (*sU)[68]  = (unsigned(*)[68])smqk;                // [128][68] i-major
    unsigned (*sV)[136] = (unsigned(*)[136])(smqk + 128 * 68);  // [64][136] k-major

    const int h = blockIdx.z, i0 = blockIdx.y * 128, j0 = blockIdx.x * 128;
    const int tid = threadIdx.x, lane = tid & 31, wid = tid >> 5;
    const int g = lane >> 2, l = lane & 3;
    const int wm0 = (wid >> 2) * 64, wn0 = (wid & 3) * 32;

    float acc[4][4][4] = {};

    #pragma unroll
    for (int ch = 0; ch < 2; ch++) {
        if (ch == 0) {
            #pragma unroll
            for (int n = 0; n < 8; n++) {       // U = q_i
                int f = tid + n * 256, i = f >> 4, d = (f & 15) * 4;
                float4 t = *(const float4*)(q + (size_t)(i0 + i) * CH + h * DH + d);
                sU[i][d] = f2t(t.x); sU[i][d + 1] = f2t(t.y);
                sU[i][d + 2] = f2t(t.z); sU[i][d + 3] = f2t(t.w);
            }
            #pragma unroll
            for (int n = 0; n < 8; n++) {       // V = k_j^T
                int f = tid + n * 256, j = f >> 4, d = (f & 15) * 4;
                float4 t = *(const float4*)(k + (size_t)(j0 + j) * CH + h * DH + d);
                sV[d][j] = f2t(t.x); sV[d + 1][j] = f2t(t.y);
                sV[d + 2][j] = f2t(t.z); sV[d + 3][j] = f2t(t.w);
            }
        } else {
            #pragma unroll
            for (int n = 0; n < 8; n++) {       // U = relw[d][i]
                int f = tid + n * 256, dd = f >> 5, i4 = (f & 31) * 4;
                float4 t = *(const float4*)(relw + (size_t)dd * CROP + i0 + i4);
                sU[i4][dd] = f2t(t.x); sU[i4 + 1][dd] = f2t(t.y);
                sU[i4 + 2][dd] = f2t(t.z); sU[i4 + 3][dd] = f2t(t.w);
            }
            #pragma unroll
            for (int n = 0; n < 8; n++) {       // V = q_j^T
                int f = tid + n * 256, j = f >> 4, d = (f & 15) * 4;
                float4 t = *(const float4*)(q + (size_t)(j0 + j) * CH + h * DH + d);
                sV[d][j] = f2t(t.x); sV[d + 1][j] = f2t(t.y);
                sV[d + 2][j] = f2t(t.z); sV[d + 3][j] = f2t(t.w);
            }
        }
        __syncthreads();
        #pragma unroll
        for (int ks = 0; ks < 8; ks++) {
            int kk = ks * 8;
            unsigned af[4][4], bf[4][2];
            #pragma unroll
            for (int mt = 0; mt < 4; mt++) {
                int m = wm0 + mt * 16 + g;
                af[mt][0] = sU[m][kk + l];       af[mt][1] = sU[m + 8][kk + l];
                af[mt][2] = sU[m][kk + 4 + l];   af[mt][3] = sU[m + 8][kk + 4 + l];
            }
            #pragma unroll
            for (int nt = 0; nt < 4; nt++) {
                int n = wn0 + nt * 8 + g;
                bf[nt][0] = sV[kk + l][n];       bf[nt][1] = sV[kk + 4 + l][n];
            }
            #pragma unroll
            for (int mt = 0; mt < 4; mt++)
                #pragma unroll
                for (int nt = 0; nt < 4; nt++) mma8(acc[mt][nt], af[mt], bf[nt]);
        }
        __syncthreads();
    }

    const float scale = 0.03125f;   // 1/sqrt(1024)
    #pragma unroll
    for (int mt = 0; mt < 4; mt++)
        #pragma unroll
        for (int nt = 0; nt < 4; nt++) {
            int m = i0 + wm0 + mt * 16 + g, n = j0 + wn0 + nt * 8 + 2 * l;
            size_t o0 = ((size_t)h * SEQ + m) * SEQ + n;
            size_t o1 = o0 + (size_t)8 * SEQ;
            float2 p0 = *(const float2*)(prev + o0);
            float2 p1 = *(const float2*)(prev + o1);
            *(float2*)(out + o0) = make_float2(fmaf(acc[mt][nt][0], scale, p0.x),
                                               fmaf(acc[mt][nt][1], scale, p0.y));
            *(float2*)(out + o1) = make_float2(fmaf(acc[mt][nt][2], scale, p1.x),
                                               fmaf(acc[mt][nt][3], scale, p1.y));
        }
}

// =================================================================================
// Fused online-softmax + A@V (flash style). Reads qk once; no A materialization.
// Grid: (SEQ/128, NB). Each block: 128 rows x full 2048 cols -> o[128 x 64].
// =================================================================================
__global__ __launch_bounds__(256) void fused_sm_av(const float* __restrict__ qk,
                                                   const float* __restrict__ v,
                                                   float* __restrict__ o) {
    extern __shared__ char smraw[];
    float*    sPf  = (float*)smraw;                     // [128][132] raw qk tile
    unsigned* sPu  = (unsigned*)smraw;                  // same storage, tf32 P
    unsigned (*sV)[72] = (unsigned(*)[72])(smraw + 128 * 132 * 4);   // [128][72]
    float* sm_m = (float*)(smraw + 128 * 132 * 4 + 128 * 72 * 4);
    float* sm_s = sm_m + 128;
    float* sm_c = sm_s + 128;

    const int h = blockIdx.y, i0 = blockIdx.x * 128;
    const int tid = threadIdx.x, lane = tid & 31, wid = tid >> 5;
    const int g = lane >> 2, l = lane & 3;
    const int wm0 = (wid >> 1) * 32, wn0 = (wid & 1) * 32;

    float acc[2][4][4] = {};
    if (tid < 128) { sm_m[tid] = -1e30f; sm_s[tid] = 0.f; }
    __syncthreads();

    const float* qkh = qk + ((size_t)h * SEQ + i0) * SEQ;
    const int rr = tid >> 1, cb = (tid & 1) * 64;

    for (int jt = 0; jt < 16; jt++) {
        const int j0 = jt * 128;
        // load qk tile (fp32) + V tile (tf32)
        #pragma unroll
        for (int n = 0; n < 16; n++) {
            int f = tid + n * 256, r = f >> 5, c4 = (f & 31) * 4;
            *(float4*)&sPf[r * 132 + c4] = *(const float4*)(qkh + (size_t)r * SEQ + j0 + c4);
        }
        #pragma unroll
        for (int n = 0; n < 8; n++) {
            int f = tid + n * 256, r = f >> 4, c4 = (f & 15) * 4;
            float4 t = *(const float4*)(v + (size_t)(j0 + r) * CH + h * DH + c4);
            sV[r][c4] = f2t(t.x); sV[r][c4 + 1] = f2t(t.y);
            sV[r][c4 + 2] = f2t(t.z); sV[r][c4 + 3] = f2t(t.w);
        }
        __syncthreads();

        // row stats: 2 threads per row, 64 elems each
        float mx = -1e30f;
        #pragma unroll
        for (int jj = 0; jj < 16; jj++) {
            float4 t = *(float4*)&sPf[rr * 132 + cb + jj * 4];
            mx = fmaxf(mx, fmaxf(fmaxf(t.x, t.y), fmaxf(t.z, t.w)));
        }
        mx = fmaxf(mx, __shfl_xor_sync(~0u, mx, 1));
        float m_old = sm_m[rr];
        float m_new = fmaxf(m_old, mx);
        float sc = __expf(m_old - m_new);
        if ((tid & 1) == 0) { sm_m[rr] = m_new; sm_c[rr] = sc; }

        // exp in place (fp32 -> tf32) + row sum
        float sum = 0.f;
        #pragma unroll
        for (int jj = 0; jj < 16; jj++) {
            float4 t = *(float4*)&sPf[rr * 132 + cb + jj * 4];
            float e0 = __expf(t.x - m_new), e1 = __expf(t.y - m_new);
            float e2 = __expf(t.z - m_new), e3 = __expf(t.w - m_new);
            sum += (e0 + e1) + (e2 + e3);
            *(uint4*)&sPu[rr * 132 + cb + jj * 4] =
                make_uint4(f2t(e0), f2t(e1), f2t(e2), f2t(e3));
        }
        sum += __shfl_xor_sync(~0u, sum, 1);
        if ((tid & 1) == 0) sm_s[rr] = sm_s[rr] * sc + sum;
        __syncthreads();

        // rescale acc, then P @ V
        #pragma unroll
        for (int mt = 0; mt < 2; mt++) {
            int m = wm0 + mt * 16 + g;
            float s0 = sm_c[m], s1 = sm_c[m + 8];
            #pragma unroll
            for (int nt = 0; nt < 4; nt++) {
                acc[mt][nt][0] *= s0; acc[mt][nt][1] *= s0;
                acc[mt][nt][2] *= s1; acc[mt][nt][3] *= s1;
            }
        }
        #pragma unroll
        for (int ks = 0; ks < 16; ks++) {
            int kk = ks * 8;
            unsigned af[2][4], bf[4][2];
            #pragma unroll
            for (int mt = 0; mt < 2; mt++) {
                int m = wm0 + mt * 16 + g;
                af[mt][0] = sPu[m * 132 + kk + l];
                af[mt][1] = sPu[(m + 8) * 132 + kk + l];
                af[mt][2] = sPu[m * 132 + kk + 4 + l];
                af[mt][3] = sPu[(m + 8) * 132 + kk + 4 + l];
            }
            #pragma unroll
            for (int nt = 0; nt < 4; nt++) {
                int n = wn0 + nt * 8 + g;
                bf[nt][0] = sV[kk + l][n];       bf[nt][1] = sV[kk + 4 + l][n];
            }
            #pragma unroll
            for (int mt = 0; mt < 2; mt++)
                #pragma unroll
                for (int nt = 0; nt < 4; nt++) mma8(acc[mt][nt], af[mt], bf[nt]);
        }
        __syncthreads();
    }

    // normalize + store
    #pragma unroll
    for (int mt = 0; mt < 2; mt++) {
        int m = wm0 + mt * 16 + g;
        float inv0 = 1.0f / sm_s[m], inv1 = 1.0f / sm_s[m + 8];
        #pragma unroll
        for (int nt = 0; nt < 4; nt++) {
            int n = wn0 + nt * 8 + 2 * l;
            *(float2*)(o + (size_t)(i0 + m) * CH + h * DH + n) =
                make_float2(acc[mt][nt][0] * inv0, acc[mt][nt][1] * inv0);
            *(float2*)(o + (size_t)(i0 + m + 8) * CH + h * DH + n) =
                make_float2(acc[mt][nt][2] * inv1, acc[mt][nt][3] * inv1);
        }
    }
}

// =================================================================================
extern "C" void kernel_launch(void* const* d_in, const int* in_sizes, int n_in,
                              void* d_out, int out_size) {
    const float* x    = (const float*)d_in[0];
    const float* prev = (const float*)d_in[1];
    const float* Wq   = (const float*)d_in[2];
    const float* Wk   = (const float*)d_in[3];
    const float* Wv   = (const float*)d_in[4];
    const float* Wo   = (const float*)d_in[5];
    const float* cq   = (const float*)d_in[6];
    const float* ck   = (const float*)d_in[7];
    const float* cv   = (const float*)d_in[8];
    const float* relw = (const float*)d_in[9];

    float* out0 = (float*)d_out;

    float *xq, *xk, *xv, *q, *k, *v, *o, *qks;
    cudaGetSymbolAddress((void**)&xq, g_xq);
    cudaGetSymbolAddress((void**)&xk, g_xk);
    cudaGetSymbolAddress((void**)&xv, g_xv);
    cudaGetSymbolAddress((void**)&q,  g_q);
    cudaGetSymbolAddress((void**)&k,  g_k);
    cudaGetSymbolAddress((void**)&v,  g_v);
    cudaGetSymbolAddress((void**)&o,  g_o);
    cudaGetSymbolAddress((void**)&qks, g_qk);

    const long long need = (long long)SEQ * CH + (long long)NB * SEQ * SEQ;
    float* qk_dst = ((long long)out_size >= need) ? (out0 + (size_t)SEQ * CH) : qks;

    const int SMEM_QK = (128 * 68 + 64 * 136) * (int)sizeof(unsigned);        // 69632
    const int SMEM_F  = (128 * 132 + 128 * 72 + 3 * 128) * (int)sizeof(float); // 105984
    cudaFuncSetAttribute(qk_tf32, cudaFuncAttributeMaxDynamicSharedMemorySize, SMEM_QK);
    cudaFuncSetAttribute(fused_sm_av, cudaFuncAttributeMaxDynamicSharedMemorySize, SMEM_F);

    gemm_xw<<<dim3(CH / 128, SEQ / 128, 3), 256>>>(x, Wq, Wk, Wv, xq, xk, xv);

    dwconv3<<<dim3(SEQ * CH / 256, 3), 256>>>(xq, xk, xv, cq, ck, cv, q, k, v);

    qk_tf32<<<dim3(SEQ / 128, SEQ / 128, NB), 256, SMEM_QK>>>(q, k, relw, prev, qk_dst);

    fused_sm_av<<<dim3(SEQ / 128, NB), 256, SMEM_F>>>(qk_dst, v, o);

    gemm_xw<<<dim3(CH / 128, SEQ / 128, 1), 256>>>(o, Wo, Wo, Wo, out0, out0, out0);
}